// round 4
// baseline (speedup 1.0000x reference)
#include <cuda_runtime.h>
#include <math.h>

// Problem shape (fixed by dataset): B=256, T=1024, H=128, FUTURE=32.
#define BB    256
#define HH    128
#define KK1   129          // cell1 input  [x, h1_prev]
#define KK2   257          // cell2 input  [x, h1_new, h2_prev]
#define KK3   385          // cell3 input  [x, h1_new, h2_new, h3_prev]
#define GRIDN 128          // persistent CTAs (<= 148 SMs, 1 CTA/SM -> co-resident)
#define NTHR  256

// ---------------- device-global state (allocation-free scratch) --------------
__device__ float g_h1[2][HH * BB];
__device__ float g_h2[2][HH * BB];
__device__ float g_h3[2][HH * BB];
__device__ unsigned g_arr;
__device__ unsigned g_gen;

__global__ void lstm_bar_init() { g_arr = 0u; g_gen = 0u; }

// ---------------- grid-wide generation barrier -------------------------------
__device__ __forceinline__ void gsync(unsigned &lg) {
    __syncthreads();
    if (threadIdx.x == 0) {
        unsigned target = lg + 1u;
        __threadfence();                       // release: this CTA's writes -> L2
        unsigned old = atomicAdd(&g_arr, 1u);
        if (old == GRIDN - 1u) {
            atomicExch(&g_arr, 0u);
            __threadfence();
            atomicExch(&g_gen, target);
        } else {
            volatile unsigned *p = &g_gen;
            while (*p < target) { }
        }
        __threadfence();                       // acquire
        lg = target;
    }
    __syncthreads();
}

// ---------------- activations ------------------------------------------------
__device__ __forceinline__ float sigf(float v) {
    return __fdividef(1.0f, 1.0f + __expf(-v));
}
__device__ __forceinline__ float tanhfast(float v) {
    // tanh(x) = 2*sigmoid(2x) - 1 ; saturates gracefully at both ends
    return 2.0f * sigf(2.0f * v) - 1.0f;
}

// ---------------- one LSTM cell for this thread ------------------------------
// wsq: [K][8] float4 (4 gates i,f,g,o for local row j at input k)
// in_s: [K][32] floats (input vector per batch lane)
template <int K>
__device__ __forceinline__ float cell_eval(const float4 *__restrict__ wsq,
                                           float4 acc,
                                           const float *__restrict__ in_s,
                                           int lane, int j, float &cst) {
    const float4 *wp = wsq + j;
    const float  *ip = in_s + lane;
#pragma unroll 4
    for (int k = 0; k < K; k++) {
        float4 w = wp[k * 8];                  // LDS.128 broadcast (lane-uniform)
        float  v = ip[k * 32];                 // conflict-free (consecutive lanes)
        acc.x = fmaf(w.x, v, acc.x);
        acc.y = fmaf(w.y, v, acc.y);
        acc.z = fmaf(w.z, v, acc.z);
        acc.w = fmaf(w.w, v, acc.w);
    }
    float ig = sigf(acc.x);
    float fg = sigf(acc.y);
    float gg = tanhfast(acc.z);
    float og = sigf(acc.w);
    cst = fg * cst + ig * gg;
    return og * tanhfast(cst);
}

// ---------------- smem layout (floats) ---------------------------------------
#define WS1_F   (KK1 * 32)          // 4128
#define WS2_F   (KK2 * 32)          // 8224
#define WS3_F   (KK3 * 32)          // 12320
#define BIAS_F  96
#define WL_F    392                 // 385 weights + bias + pad
#define ABUF_F  (KK1 * 32)          // cell1 input buffer
#define BIG_F   (KK3 * 32)          // shared input buffer [x,h1,h2,h3]
#define PO_F    256
#define OX_F    32
#define SMEM_FLOATS (WS1_F + WS2_F + WS3_F + BIAS_F + WL_F + ABUF_F + BIG_F + PO_F + OX_F)
#define SMEM_BYTES  (SMEM_FLOATS * 4)

__global__ void __launch_bounds__(NTHR, 1)
lstm_persist_kernel(const float *__restrict__ x,
                    const float *__restrict__ Wi1, const float *__restrict__ Wh1,
                    const float *__restrict__ bi1, const float *__restrict__ bh1,
                    const float *__restrict__ Wi2, const float *__restrict__ Wh2,
                    const float *__restrict__ bi2, const float *__restrict__ bh2,
                    const float *__restrict__ Wi3, const float *__restrict__ Wh3,
                    const float *__restrict__ bi3, const float *__restrict__ bh3,
                    const float *__restrict__ Wl,  const float *__restrict__ bl,
                    float *__restrict__ out, int T, int NT) {
    extern __shared__ float sm[];
    float *ws1f = sm;
    float *ws2f = ws1f + WS1_F;
    float *ws3f = ws2f + WS2_F;
    float *biasf = ws3f + WS3_F;
    float *wl   = biasf + BIAS_F;
    float *abuf = wl + WL_F;
    float *big  = abuf + ABUF_F;
    float *po_s = big + BIG_F;
    float *ox   = po_s + PO_F;

    const float4 *ws1 = (const float4 *)ws1f;
    const float4 *ws2 = (const float4 *)ws2f;
    const float4 *ws3 = (const float4 *)ws3f;
    const float4 *bias4 = (const float4 *)biasf;

    const int tid  = threadIdx.x;
    const int lane = tid & 31;
    const int j    = tid >> 5;             // warp id == local hidden row
    const int hg   = blockIdx.x & 15;      // hidden group (16)
    const int bg   = blockIdx.x >> 4;      // batch group (8)
    const int bcol = bg * 32 + lane;       // global batch column
    const int r    = hg * 8 + j;           // global hidden row (per gate block)
    unsigned lg = 0;

    // ---- stage per-CTA weight slices once (layout [k][j][gate]) -------------
    for (int idx = tid; idx < WS1_F; idx += NTHR) {
        int k = idx >> 5, t5 = idx & 31, jj = t5 >> 2, g = t5 & 3;
        int row = g * HH + hg * 8 + jj;
        ws1f[idx] = (k == 0) ? Wi1[row] : Wh1[row * HH + (k - 1)];
    }
    for (int idx = tid; idx < WS2_F; idx += NTHR) {
        int k = idx >> 5, t5 = idx & 31, jj = t5 >> 2, g = t5 & 3;
        int row = g * HH + hg * 8 + jj;
        ws2f[idx] = (k < KK1) ? Wi2[row * KK1 + k] : Wh2[row * HH + (k - KK1)];
    }
    for (int idx = tid; idx < WS3_F; idx += NTHR) {
        int k = idx >> 5, t5 = idx & 31, jj = t5 >> 2, g = t5 & 3;
        int row = g * HH + hg * 8 + jj;
        ws3f[idx] = (k < 257) ? Wi3[row * 257 + k] : Wh3[row * HH + (k - 257)];
    }
    if (tid < 96) {
        int cell = tid >> 5, t5 = tid & 31, jj = t5 >> 2, g = t5 & 3;
        int row = g * HH + hg * 8 + jj;
        float b;
        if (cell == 0)      b = bi1[row] + bh1[row];
        else if (cell == 1) b = bi2[row] + bh2[row];
        else                b = bi3[row] + bh3[row];
        biasf[cell * 32 + t5] = b;
    }
    for (int idx = tid; idx < 385; idx += NTHR) wl[idx] = Wl[idx];
    if (tid == 0) wl[385] = bl[0];
    if (tid < 32) ox[tid] = 0.0f;

    // zero this CTA's slice of h state buffer 0 ("old" at t=0)
    for (int idx = tid; idx < 8 * 32; idx += NTHR) {
        int rr = hg * 8 + (idx >> 5);
        int cc = bg * 32 + (idx & 31);
        g_h1[0][rr * BB + cc] = 0.0f;
        g_h2[0][rr * BB + cc] = 0.0f;
        g_h3[0][rr * BB + cc] = 0.0f;
    }
    float c1 = 0.0f, c2 = 0.0f, c3 = 0.0f;
    gsync(lg);

    for (int t = 0; t < NT; t++) {
        const int po = t & 1, pn = po ^ 1;

        // ---- stage step inputs: x_t, h1_prev (abuf), h2_prev/h3_prev (big) --
        if (tid < 32) {
            float xv = (t < T) ? __ldg(&x[(bg * 32 + tid) * T + t]) : ox[tid];
            abuf[tid] = xv;
            big[tid]  = xv;
        }
        {
            const float *s1 = &g_h1[po][bg * 32];
            const float *s2 = &g_h2[po][bg * 32];
            const float *s3 = &g_h3[po][bg * 32];
            float *d1 = abuf + 32;
            float *d2 = big + 129 * 32;
            float *d3 = big + 257 * 32;
            for (int idx = tid; idx < HH * 32; idx += NTHR) {
                int gi = (idx >> 5) * BB + (idx & 31);
                d1[idx] = __ldcg(s1 + gi);
                d2[idx] = __ldcg(s2 + gi);
                d3[idx] = __ldcg(s3 + gi);
            }
        }
        __syncthreads();

        // ---- cell 1 ---------------------------------------------------------
        float h1v = cell_eval<KK1>(ws1, bias4[0 * 8 + j], abuf, lane, j, c1);
        g_h1[pn][r * BB + bcol] = h1v;
        gsync(lg);

        // stage h1_new into big slots 1..128
        {
            const float *s1 = &g_h1[pn][bg * 32];
            float *d1 = big + 32;
            for (int idx = tid; idx < HH * 32; idx += NTHR)
                d1[idx] = __ldcg(s1 + (idx >> 5) * BB + (idx & 31));
        }
        __syncthreads();

        // ---- cell 2 ---------------------------------------------------------
        float h2v = cell_eval<KK2>(ws2, bias4[1 * 8 + j], big, lane, j, c2);
        g_h2[pn][r * BB + bcol] = h2v;
        gsync(lg);

        // stage h2_new into big slots 129..256
        {
            const float *s2 = &g_h2[pn][bg * 32];
            float *d2 = big + 129 * 32;
            for (int idx = tid; idx < HH * 32; idx += NTHR)
                d2[idx] = __ldcg(s2 + (idx >> 5) * BB + (idx & 31));
        }
        __syncthreads();

        // ---- cell 3 ---------------------------------------------------------
        float h3v = cell_eval<KK3>(ws3, bias4[2 * 8 + j], big, lane, j, c3);
        g_h3[pn][r * BB + bcol] = h3v;
        gsync(lg);

        // stage h3_new into big slots 257..384 (overwrites h3_prev; done with it)
        {
            const float *s3 = &g_h3[pn][bg * 32];
            float *d3 = big + 257 * 32;
            for (int idx = tid; idx < HH * 32; idx += NTHR)
                d3[idx] = __ldcg(s3 + (idx >> 5) * BB + (idx & 31));
        }
        __syncthreads();

        // ---- linear head: o_t = [x,h1,h2,h3] . Wl + b (every CTA, own cols) -
        {
            const int sub = tid >> 5;
            float p = 0.0f;
            for (int k = sub; k < 385; k += 8)
                p = fmaf(wl[k], big[k * 32 + lane], p);
            po_s[sub * 32 + lane] = p;
            __syncthreads();
            if (tid < 32) {
                float o = wl[385];
#pragma unroll
                for (int s = 0; s < 8; s++) o += po_s[s * 32 + tid];
                ox[tid] = o;                                    // feedback x_{t+1}
                if (hg == 0) out[(bg * 32 + tid) * NT + t] = o; // one writer group
            }
            __syncthreads();
        }
    }
}

extern "C" void kernel_launch(void* const* d_in, const int* in_sizes, int n_in,
                              void* d_out, int out_size) {
    const float *x   = (const float *)d_in[0];
    const float *Wi1 = (const float *)d_in[1];
    const float *Wh1 = (const float *)d_in[2];
    const float *bi1 = (const float *)d_in[3];
    const float *bh1 = (const float *)d_in[4];
    const float *Wi2 = (const float *)d_in[5];
    const float *Wh2 = (const float *)d_in[6];
    const float *bi2 = (const float *)d_in[7];
    const float *bh2 = (const float *)d_in[8];
    const float *Wi3 = (const float *)d_in[9];
    const float *Wh3 = (const float *)d_in[10];
    const float *bi3 = (const float *)d_in[11];
    const float *bh3 = (const float *)d_in[12];
    const float *Wl  = (const float *)d_in[13];
    const float *bl  = (const float *)d_in[14];
    float *out = (float *)d_out;

    int T  = in_sizes[0] / BB;   // 1024
    int NT = out_size / BB;      // 1056

    cudaFuncSetAttribute(lstm_persist_kernel,
                         cudaFuncAttributeMaxDynamicSharedMemorySize, SMEM_BYTES);

    lstm_bar_init<<<1, 1>>>();
    lstm_persist_kernel<<<GRIDN, NTHR, SMEM_BYTES>>>(
        x, Wi1, Wh1, bi1, bh1, Wi2, Wh2, bi2, bh2,
        Wi3, Wh3, bi3, bh3, Wl, bl, out, T, NT);
}